// round 1
// baseline (speedup 1.0000x reference)
#include <cuda_runtime.h>
#include <math.h>

#define SEQ 2048
#define HDIM 2048
#define NH 16
#define NKV 4
#define HD 128
#define RD 64
#define NE 16
#define FF 512
#define TKN 4

// ------------------------- scratch (static device memory; no cudaMalloc) ---
__device__ float g_xn[SEQ * HDIM];
__device__ float g_qraw[SEQ * NH * HD];
__device__ float g_kraw[SEQ * NKV * HD];
__device__ float g_vraw[SEQ * NKV * HD];
__device__ float g_qT[NH * SEQ * HD];
__device__ float g_kT[NKV * SEQ * HD];
__device__ float g_vT[NKV * SEQ * HD];
__device__ float g_scores[(size_t)NH * SEQ * SEQ];   // 256 MB
__device__ float g_ao[SEQ * HDIM];
__device__ float g_h1[SEQ * HDIM];
__device__ float g_xf[SEQ * HDIM];
__device__ float g_gbuf[NE * SEQ * FF];              // 64 MB
__device__ float g_ubuf[NE * SEQ * FF];              // 64 MB
__device__ float g_slot[TKN * SEQ * HDIM];           // 64 MB
__device__ int   g_cnt[NE];
__device__ int   g_tok[NE * SEQ];
__device__ int   g_orow[NE * SEQ];
__device__ float g_wt[NE * SEQ];

// ------------------------- generic fp32 tiled GEMM -------------------------
// C[M,N] = A[M,K] @ op(B), optional +resid, batched over z.
//   TB: B is [N,K] (transposed) instead of [K,N]
//   Aidx: per-z row gather for A (stride SEQ); Cidx: per-z row scatter for C
//   cnt:  per-z M override (MoE); causal: skip tiles with n0 > m0+127
template<bool TB>
__launch_bounds__(256)
__global__ void sgemm_k(const float* __restrict__ A, const float* __restrict__ B,
                        float* __restrict__ C, const float* __restrict__ resid,
                        int M, int N, int K, int lda, int ldb, int ldc,
                        long long sA, long long sB, long long sC, int bzdiv,
                        const int* __restrict__ Aidx, const int* __restrict__ Cidx,
                        const int* __restrict__ cnt, int causal)
{
    int z = blockIdx.z;
    if (cnt) M = cnt[z];
    int m0 = blockIdx.y * 128, n0 = blockIdx.x * 128;
    if (m0 >= M) return;
    if (causal && n0 > m0 + 127) return;

    const float* Az = A + sA * z;
    const float* Bz = B + sB * (z / bzdiv);
    const int* aidx = Aidx ? Aidx + (size_t)z * SEQ : nullptr;
    const int* cidx = Cidx ? Cidx + (size_t)z * SEQ : nullptr;

    __shared__ float As[8][128];
    __shared__ float Bs[8][128];

    int tid = threadIdx.x;
    int tr = (tid >> 4) << 3;
    int tc = (tid & 15) << 3;

    float acc[8][8];
#pragma unroll
    for (int i = 0; i < 8; i++)
#pragma unroll
        for (int j = 0; j < 8; j++) acc[i][j] = 0.f;

    for (int k0 = 0; k0 < K; k0 += 8) {
#pragma unroll
        for (int c = 0; c < 4; c++) {
            int flat = tid + (c << 8);
            int m = flat >> 3, kk = flat & 7;
            int gm = m0 + m;
            float v = 0.f;
            if (gm < M) {
                int ar = aidx ? aidx[gm] : gm;
                v = Az[(size_t)ar * lda + k0 + kk];
            }
            As[kk][m] = v;
        }
#pragma unroll
        for (int c = 0; c < 4; c++) {
            int flat = tid + (c << 8);
            if (TB) {
                int n = flat >> 3, kk = flat & 7;
                Bs[kk][n] = Bz[(size_t)(n0 + n) * ldb + k0 + kk];
            } else {
                int kk = flat >> 7, n = flat & 127;
                Bs[kk][n] = Bz[(size_t)(k0 + kk) * ldb + n0 + n];
            }
        }
        __syncthreads();
#pragma unroll
        for (int kk = 0; kk < 8; kk++) {
            float a[8], b[8];
#pragma unroll
            for (int i = 0; i < 8; i++) a[i] = As[kk][tr + i];
#pragma unroll
            for (int j = 0; j < 8; j++) b[j] = Bs[kk][tc + j];
#pragma unroll
            for (int i = 0; i < 8; i++)
#pragma unroll
                for (int j = 0; j < 8; j++) acc[i][j] += a[i] * b[j];
        }
        __syncthreads();
    }

    float* Cz = C + sC * z;
#pragma unroll
    for (int i = 0; i < 8; i++) {
        int gm = m0 + tr + i;
        if (gm >= M) continue;
        int cr = cidx ? cidx[gm] : gm;
        float* cp = Cz + (size_t)cr * ldc + n0 + tc;
        if (resid) {
            const float* rp = resid + (size_t)cr * ldc + n0 + tc;
#pragma unroll
            for (int j = 0; j < 8; j++) cp[j] = acc[i][j] + rp[j];
        } else {
#pragma unroll
            for (int j = 0; j < 8; j++) cp[j] = acc[i][j];
        }
    }
}

// ------------------------- elementwise / reduction kernels ------------------
__global__ void rmsnorm_k(const float* __restrict__ x, const float* __restrict__ w,
                          float* __restrict__ o)
{
    int t = blockIdx.x, tid = threadIdx.x;
    const float* xr = x + (size_t)t * HDIM;
    float s = 0.f;
    for (int h = tid; h < HDIM; h += 256) { float v = xr[h]; s += v * v; }
    __shared__ float red[256];
    red[tid] = s; __syncthreads();
    for (int st = 128; st > 0; st >>= 1) {
        if (tid < st) red[tid] += red[tid + st];
        __syncthreads();
    }
    float inv = rsqrtf(red[0] / (float)HDIM + 1e-6f);
    float* orow = o + (size_t)t * HDIM;
    for (int h = tid; h < HDIM; h += 256) orow[h] = w[h] * xr[h] * inv;
}

__global__ void rope_k(const float* __restrict__ raw, const float* __restrict__ cosb,
                       const float* __restrict__ sinb, float* __restrict__ outT, int nheads)
{
    int s = blockIdx.x, h = blockIdx.y, d = threadIdx.x;
    const float* r = raw + (size_t)s * nheads * HD + (size_t)h * HD;
    float v;
    if (d < 32)      v = r[d] * cosb[s * RD + d] - r[d + 32] * sinb[s * RD + d];
    else if (d < 64) v = r[d] * cosb[s * RD + d] + r[d - 32] * sinb[s * RD + d];
    else             v = r[d];
    outT[((size_t)h * SEQ + s) * HD + d] = v;
}

__global__ void transv_k(const float* __restrict__ raw, float* __restrict__ outT, int nheads)
{
    int s = blockIdx.x, h = blockIdx.y, d = threadIdx.x;
    outT[((size_t)h * SEQ + s) * HD + d] = raw[(size_t)s * nheads * HD + (size_t)h * HD + d];
}

__global__ void softmax_k(float* __restrict__ sc, const float* __restrict__ sink)
{
    int i = blockIdx.x, h = blockIdx.y, tid = threadIdx.x;
    float* row = sc + ((size_t)h * SEQ + i) * (size_t)SEQ;
    const float scale = 0.08838834764831845f;   // 128^-0.5
    __shared__ float red[256];

    float m = -1e30f;
    for (int j = tid; j <= i; j += 256) m = fmaxf(m, row[j] * scale);
    red[tid] = m; __syncthreads();
    for (int st = 128; st > 0; st >>= 1) {
        if (tid < st) red[tid] = fmaxf(red[tid], red[tid + st]);
        __syncthreads();
    }
    m = red[0]; __syncthreads();

    float ssum = 0.f;
    for (int j = tid; j <= i; j += 256) ssum += expf(row[j] * scale - m);
    red[tid] = ssum; __syncthreads();
    for (int st = 128; st > 0; st >>= 1) {
        if (tid < st) red[tid] += red[tid + st];
        __syncthreads();
    }
    float denom = red[0] + expf(sink[h] - m);
    float inv = 1.f / denom;

    for (int j = tid; j < SEQ; j += 256)
        row[j] = (j <= i) ? expf(row[j] * scale - m) * inv : 0.f;
}

__global__ void zero_cnt_k(int* cnt) { if (threadIdx.x < NE) cnt[threadIdx.x] = 0; }

__global__ void router_k(const float* __restrict__ xf, const float* __restrict__ gw,
                         const float* __restrict__ gbias, int* cnt, int* tok,
                         int* orow, float* wt)
{
    int t = blockIdx.x, tid = threadIdx.x;
    int lane = tid & 31, wid = tid >> 5;
    __shared__ float logits[NE];
    const float* xr = xf + (size_t)t * HDIM;

    for (int e = wid; e < NE; e += 8) {
        const float* gr = gw + (size_t)e * HDIM;
        float p = 0.f;
        for (int hh = lane; hh < HDIM; hh += 32) p += xr[hh] * gr[hh];
        for (int off = 16; off > 0; off >>= 1) p += __shfl_down_sync(0xffffffffu, p, off);
        if (lane == 0) logits[e] = p;
    }
    __syncthreads();

    if (tid == 0) {
        float sg[NE], sfc[NE];
        for (int e = 0; e < NE; e++) {
            sg[e] = 1.f / (1.f + expf(-logits[e]));
            sfc[e] = sg[e] + gbias[e];
        }
        // group scores: sum of top-2 inside each group of 4
        float gs[4];
        for (int g = 0; g < 4; g++) {
            float m1 = -1e30f, m2 = -1e30f;
            for (int j = 0; j < 4; j++) {
                float v = sfc[g * 4 + j];
                if (v > m1) { m2 = m1; m1 = v; } else if (v > m2) m2 = v;
            }
            gs[g] = m1 + m2;
        }
        int g1 = 0;
        for (int g = 1; g < 4; g++) if (gs[g] > gs[g1]) g1 = g;
        int g2 = -1;
        for (int g = 0; g < 4; g++) {
            if (g == g1) continue;
            if (g2 < 0 || gs[g] > gs[g2]) g2 = g;
        }
        bool allow[NE];
        for (int e = 0; e < NE; e++) { int g = e >> 2; allow[e] = (g == g1 || g == g2); }

        int idx[TKN]; float tws[TKN]; float sum = 0.f;
        bool used[NE] = {};
        for (int j = 0; j < TKN; j++) {
            int bi = -1; float bv = -1e30f;
            for (int e = 0; e < NE; e++)
                if (allow[e] && !used[e] && sfc[e] > bv) { bv = sfc[e]; bi = e; }
            used[bi] = true; idx[j] = bi; tws[j] = sg[bi]; sum += tws[j];
        }
        float invs = 2.5f / (sum + 1e-20f);
        for (int j = 0; j < TKN; j++) {
            int e = idx[j];
            int pos = atomicAdd(&cnt[e], 1);
            tok[e * SEQ + pos]  = t;
            orow[e * SEQ + pos] = j * SEQ + t;
            wt[e * SEQ + pos]   = tws[j] * invs;
        }
    }
}

__global__ void silu_k(float* __restrict__ gbuf, const float* __restrict__ ubuf,
                       const float* __restrict__ wt, const int* __restrict__ cnt)
{
    int e = blockIdx.y, r = blockIdx.x;
    if (r >= cnt[e]) return;
    float w = wt[e * SEQ + r];
    size_t base = ((size_t)e * SEQ + r) * FF;
    for (int f = threadIdx.x; f < FF; f += 256) {
        float gv = gbuf[base + f], uv = ubuf[base + f];
        float sig = 1.f / (1.f + expf(-gv));
        gbuf[base + f] = gv * sig * uv * w;
    }
}

__global__ void final_k(const float* __restrict__ h1, const float* __restrict__ slot,
                        float* __restrict__ out)
{
    size_t i = (size_t)blockIdx.x * 256 + threadIdx.x;
    const size_t NTOT = (size_t)SEQ * HDIM;
    out[i] = h1[i] + slot[i] + slot[NTOT + i] + slot[2 * NTOT + i] + slot[3 * NTOT + i];
}

// ------------------------- launch ------------------------------------------
extern "C" void kernel_launch(void* const* d_in, const int* in_sizes, int n_in,
                              void* d_out, int out_size)
{
    const float* x      = (const float*)d_in[0];
    const float* cosb   = (const float*)d_in[1];
    const float* sinb   = (const float*)d_in[2];
    const float* ln1    = (const float*)d_in[3];
    const float* ln2    = (const float*)d_in[4];
    const float* Wq     = (const float*)d_in[5];
    const float* Wk     = (const float*)d_in[6];
    const float* Wv     = (const float*)d_in[7];
    const float* Wo     = (const float*)d_in[8];
    const float* sink   = (const float*)d_in[9];
    const float* gate_w = (const float*)d_in[10];
    const float* gate_b = (const float*)d_in[11];
    const float* Weg    = (const float*)d_in[12];
    const float* Weu    = (const float*)d_in[13];
    const float* Wed    = (const float*)d_in[14];
    float* out = (float*)d_out;

    void *p_xn, *p_qraw, *p_kraw, *p_vraw, *p_qT, *p_kT, *p_vT, *p_sc, *p_ao,
         *p_h1, *p_xf, *p_gb, *p_ub, *p_slot, *p_cnt, *p_tok, *p_orow, *p_wt;
    cudaGetSymbolAddress(&p_xn, g_xn);
    cudaGetSymbolAddress(&p_qraw, g_qraw);
    cudaGetSymbolAddress(&p_kraw, g_kraw);
    cudaGetSymbolAddress(&p_vraw, g_vraw);
    cudaGetSymbolAddress(&p_qT, g_qT);
    cudaGetSymbolAddress(&p_kT, g_kT);
    cudaGetSymbolAddress(&p_vT, g_vT);
    cudaGetSymbolAddress(&p_sc, g_scores);
    cudaGetSymbolAddress(&p_ao, g_ao);
    cudaGetSymbolAddress(&p_h1, g_h1);
    cudaGetSymbolAddress(&p_xf, g_xf);
    cudaGetSymbolAddress(&p_gb, g_gbuf);
    cudaGetSymbolAddress(&p_ub, g_ubuf);
    cudaGetSymbolAddress(&p_slot, g_slot);
    cudaGetSymbolAddress(&p_cnt, g_cnt);
    cudaGetSymbolAddress(&p_tok, g_tok);
    cudaGetSymbolAddress(&p_orow, g_orow);
    cudaGetSymbolAddress(&p_wt, g_wt);

    float* xn   = (float*)p_xn;
    float* qraw = (float*)p_qraw;  float* kraw = (float*)p_kraw;  float* vraw = (float*)p_vraw;
    float* qT   = (float*)p_qT;    float* kT   = (float*)p_kT;    float* vT   = (float*)p_vT;
    float* sc   = (float*)p_sc;    float* ao   = (float*)p_ao;    float* h1   = (float*)p_h1;
    float* xf   = (float*)p_xf;    float* gb   = (float*)p_gb;    float* ub   = (float*)p_ub;
    float* slot = (float*)p_slot;
    int* cnt = (int*)p_cnt; int* tok = (int*)p_tok; int* orow = (int*)p_orow;
    float* wt = (float*)p_wt;

    zero_cnt_k<<<1, 32>>>(cnt);

    // xn = rmsnorm(x, ln1)
    rmsnorm_k<<<SEQ, 256>>>(x, ln1, xn);

    // QKV projections
    sgemm_k<false><<<dim3(HDIM / 128, SEQ / 128, 1), 256>>>(
        xn, Wq, qraw, nullptr, SEQ, HDIM, HDIM, HDIM, HDIM, HDIM,
        0, 0, 0, 1, nullptr, nullptr, nullptr, 0);
    sgemm_k<false><<<dim3(512 / 128, SEQ / 128, 1), 256>>>(
        xn, Wk, kraw, nullptr, SEQ, 512, HDIM, HDIM, 512, 512,
        0, 0, 0, 1, nullptr, nullptr, nullptr, 0);
    sgemm_k<false><<<dim3(512 / 128, SEQ / 128, 1), 256>>>(
        xn, Wv, vraw, nullptr, SEQ, 512, HDIM, HDIM, 512, 512,
        0, 0, 0, 1, nullptr, nullptr, nullptr, 0);

    // RoPE + [head][seq][dim] transposes
    rope_k<<<dim3(SEQ, NH), 128>>>(qraw, cosb, sinb, qT, NH);
    rope_k<<<dim3(SEQ, NKV), 128>>>(kraw, cosb, sinb, kT, NKV);
    transv_k<<<dim3(SEQ, NKV), 128>>>(vraw, vT, NKV);

    // scores[h] = qT[h] @ kT[h/4]^T  (causal tile skip)
    sgemm_k<true><<<dim3(SEQ / 128, SEQ / 128, NH), 256>>>(
        qT, kT, sc, nullptr, SEQ, SEQ, HD, HD, HD, SEQ,
        (long long)SEQ * HD, (long long)SEQ * HD, (long long)SEQ * SEQ, NH / NKV,
        nullptr, nullptr, nullptr, 1);

    // softmax with sink bias (writes zeros above the diagonal)
    softmax_k<<<dim3(SEQ, NH), 256>>>(sc, sink);

    // ao[:, h*128:(h+1)*128] = probs[h] @ vT[h/4]
    sgemm_k<false><<<dim3(1, SEQ / 128, NH), 256>>>(
        sc, vT, ao, nullptr, SEQ, HD, SEQ, SEQ, HD, HDIM,
        (long long)SEQ * SEQ, (long long)SEQ * HD, 128, NH / NKV,
        nullptr, nullptr, nullptr, 0);

    // h1 = ao @ Wo + x
    sgemm_k<false><<<dim3(HDIM / 128, SEQ / 128, 1), 256>>>(
        ao, Wo, h1, x, SEQ, HDIM, HDIM, HDIM, HDIM, HDIM,
        0, 0, 0, 1, nullptr, nullptr, nullptr, 0);

    // xf = rmsnorm(h1, ln2)
    rmsnorm_k<<<SEQ, 256>>>(h1, ln2, xf);

    // router: build per-expert gathered token lists + weights
    router_k<<<SEQ, 256>>>(xf, gate_w, gate_b, cnt, tok, orow, wt);

    // expert gate / up projections (row-gathered A)
    sgemm_k<false><<<dim3(FF / 128, SEQ / 128, NE), 256>>>(
        xf, Weg, gb, nullptr, SEQ, FF, HDIM, HDIM, FF, FF,
        0, (long long)HDIM * FF, (long long)SEQ * FF, 1, tok, nullptr, cnt, 0);
    sgemm_k<false><<<dim3(FF / 128, SEQ / 128, NE), 256>>>(
        xf, Weu, ub, nullptr, SEQ, FF, HDIM, HDIM, FF, FF,
        0, (long long)HDIM * FF, (long long)SEQ * FF, 1, tok, nullptr, cnt, 0);

    // h = silu(g)*u*route_weight  (in place into gb)
    silu_k<<<dim3(SEQ, NE), 256>>>(gb, ub, wt, cnt);

    // down projection, scattered to per-(slot,token) rows (deterministic)
    sgemm_k<false><<<dim3(HDIM / 128, SEQ / 128, NE), 256>>>(
        gb, Wed, slot, nullptr, SEQ, HDIM, FF, FF, HDIM, HDIM,
        (long long)SEQ * FF, (long long)FF * HDIM, 0, 1, nullptr, orow, cnt, 0);

    // out = h1 + sum of 4 slot contributions
    final_k<<<(SEQ * HDIM) / 256, 256>>>(h1, slot, out);
}

// round 3
// speedup vs baseline: 1.9658x; 1.9658x over previous
#include <cuda_runtime.h>
#include <math.h>
#include <stdint.h>

#define SEQ 2048
#define HDIM 2048
#define NH 16
#define NKV 4
#define HD 128
#define RD 64
#define NE 16
#define FF 512
#define TKN 4

#define TM 128
#define TN 128
#define KC 32
#define KPAD 36                     // 32 + 4 pad (floats) per smem row
#define STG_FLOATS (128 * KPAD)     // one tile (A or B) per stage
#define DSMEM_BYTES (2 * 2 * STG_FLOATS * 4)   // 2 stages x (A + B) = 73728

// ---------------------------------------------------------------- helpers
static __device__ __forceinline__ uint32_t f2tf(float f) {
    uint32_t u; asm("cvt.rna.tf32.f32 %0, %1;" : "=r"(u) : "f"(f)); return u;
}

static __device__ __forceinline__ void mma_tf32(
    float* c, const uint32_t* a, const uint32_t* b)
{
    asm volatile(
        "mma.sync.aligned.m16n8k8.row.col.f32.tf32.tf32.f32 "
        "{%0,%1,%2,%3}, {%4,%5,%6,%7}, {%8,%9}, {%0,%1,%2,%3};"
        : "+f"(c[0]), "+f"(c[1]), "+f"(c[2]), "+f"(c[3])
        : "r"(a[0]), "r"(a[1]), "r"(a[2]), "r"(a[3]), "r"(b[0]), "r"(b[1]));
}

// ---------------------------------------------------------------- scratch
__device__ float g_xn[SEQ * HDIM];
__device__ float g_qraw[SEQ * NH * HD];
__device__ float g_kraw[SEQ * NKV * HD];
__device__ float g_vraw[SEQ * NKV * HD];
__device__ float g_scores[(size_t)NH * SEQ * SEQ];
__device__ float g_ao[SEQ * HDIM];
__device__ float g_h1[SEQ * HDIM];
__device__ float g_xf[SEQ * HDIM];
__device__ float g_gbuf[NE * SEQ * FF];
__device__ float g_ubuf[NE * SEQ * FF];
__device__ float g_slot[TKN * SEQ * HDIM];
__device__ int   g_cnt[NE];
__device__ int   g_tok[NE * SEQ];
__device__ int   g_orow[NE * SEQ];
__device__ float g_wt[NE * SEQ];

// ---------------------------------------------------------------- tf32 GEMM
// C[M,N] = A[M,K] @ op(B) (+resid), batched over z.
// TB=true: B gmem is [N,K] (K contiguous). TB=false: B gmem is [K,N].
// Aidx: per-z row gather for A; Cidx: per-z row scatter for C; cnt: M override.
// causal: skip tiles with n0 > m0+127. kcausal: cap K at m0+128.
template<bool TB>
__global__ void __launch_bounds__(256) tgemm_k(
    const float* __restrict__ A, const float* __restrict__ B,
    float* __restrict__ C, const float* __restrict__ resid,
    int M, int N, int K, int lda, int ldb, int ldc,
    long long sA, long long sB, long long sC, int bzdiv,
    const int* __restrict__ Aidx, const int* __restrict__ Cidx,
    const int* __restrict__ cnt, int causal, int kcausal)
{
    int z = blockIdx.z;
    int Mz = cnt ? cnt[z] : M;
    int m0 = blockIdx.y * TM, n0 = blockIdx.x * TN;
    if (m0 >= Mz) return;
    if (causal && n0 > m0 + TM - 1) return;
    int Keff = kcausal ? min(K, m0 + TM) : K;
    int nch = Keff / KC;

    extern __shared__ float dsm[];   // [stage][A|B][128][KPAD]

    int tid  = threadIdx.x;
    int lane = tid & 31;
    int wid  = tid >> 5;
    int wm = wid & 1;        // 0..1  -> rows wm*64
    int wn = wid >> 1;       // 0..3  -> cols wn*32

    const float* Az = A + sA * z;
    const float* Bz = B + sB * (z / bzdiv);
    const int* aidx = Aidx ? Aidx + (size_t)z * SEQ : nullptr;

    // staging thread maps
    int am = tid >> 1;             // 0..127
    int ac = (tid & 1) * 16;       // 0 or 16
    const float* arow = nullptr;
    {
        int gm = m0 + am;
        if (gm < Mz) {
            int ar = aidx ? aidx[gm] : gm;
            arow = Az + (size_t)ar * lda + ac;
        }
    }
    const float* browT = TB ? (Bz + (size_t)(n0 + am) * ldb + ac) : nullptr;
    int kk0 = tid >> 5;            // 0..7   (non-TB B)
    int nn  = (tid & 31) * 4;      // 0..124

    float acc[4][4][4];
#pragma unroll
    for (int mf = 0; mf < 4; mf++)
#pragma unroll
        for (int nf = 0; nf < 4; nf++)
#pragma unroll
            for (int r = 0; r < 4; r++) acc[mf][nf][r] = 0.f;

    float4 rA[4], rB[4];

    // prologue: load tile 0
    {
#pragma unroll
        for (int j = 0; j < 4; j++)
            rA[j] = arow ? *reinterpret_cast<const float4*>(arow + 4 * j)
                         : make_float4(0.f, 0.f, 0.f, 0.f);
        if (TB) {
#pragma unroll
            for (int j = 0; j < 4; j++)
                rB[j] = *reinterpret_cast<const float4*>(browT + 4 * j);
        } else {
#pragma unroll
            for (int r = 0; r < 4; r++)
                rB[r] = *reinterpret_cast<const float4*>(
                    Bz + (size_t)(kk0 + 8 * r) * ldb + n0 + nn);
        }
    }

    for (int i = 0; i < nch; i++) {
        int s = i & 1;
        float* sAst = dsm + s * 2 * STG_FLOATS;
        float* sBst = sAst + STG_FLOATS;
        uint32_t* sA32 = reinterpret_cast<uint32_t*>(sAst);
        uint32_t* sB32 = reinterpret_cast<uint32_t*>(sBst);

        // ---- store staged tile (cvt to tf32) ----
#pragma unroll
        for (int j = 0; j < 4; j++) {
            uint32_t* p = sA32 + am * KPAD + ac + 4 * j;
            p[0] = f2tf(rA[j].x); p[1] = f2tf(rA[j].y);
            p[2] = f2tf(rA[j].z); p[3] = f2tf(rA[j].w);
        }
        if (TB) {
#pragma unroll
            for (int j = 0; j < 4; j++) {
                uint32_t* p = sB32 + am * KPAD + ac + 4 * j;
                p[0] = f2tf(rB[j].x); p[1] = f2tf(rB[j].y);
                p[2] = f2tf(rB[j].z); p[3] = f2tf(rB[j].w);
            }
        } else {
#pragma unroll
            for (int r = 0; r < 4; r++) {
                int kk = kk0 + 8 * r;
                sB32[(nn + 0) * KPAD + kk] = f2tf(rB[r].x);
                sB32[(nn + 1) * KPAD + kk] = f2tf(rB[r].y);
                sB32[(nn + 2) * KPAD + kk] = f2tf(rB[r].z);
                sB32[(nn + 3) * KPAD + kk] = f2tf(rB[r].w);
            }
        }
        __syncthreads();

        // ---- prefetch next tile into regs (LDGs overlap the MMA work) ----
        if (i + 1 < nch) {
            int k0 = (i + 1) * KC;
#pragma unroll
            for (int j = 0; j < 4; j++)
                rA[j] = arow ? *reinterpret_cast<const float4*>(arow + k0 + 4 * j)
                             : make_float4(0.f, 0.f, 0.f, 0.f);
            if (TB) {
#pragma unroll
                for (int j = 0; j < 4; j++)
                    rB[j] = *reinterpret_cast<const float4*>(browT + k0 + 4 * j);
            } else {
#pragma unroll
                for (int r = 0; r < 4; r++)
                    rB[r] = *reinterpret_cast<const float4*>(
                        Bz + (size_t)(k0 + kk0 + 8 * r) * ldb + n0 + nn);
            }
        }

        // ---- compute k-tile from smem ----
#pragma unroll
        for (int ks = 0; ks < 4; ks++) {
            uint32_t af[4][4], bf[4][2];
            int col = ks * 8 + (lane & 3);
#pragma unroll
            for (int mf = 0; mf < 4; mf++) {
                int mr = wm * 64 + mf * 16 + (lane >> 2);
                af[mf][0] = sA32[mr * KPAD + col];
                af[mf][1] = sA32[(mr + 8) * KPAD + col];
                af[mf][2] = sA32[mr * KPAD + col + 4];
                af[mf][3] = sA32[(mr + 8) * KPAD + col + 4];
            }
#pragma unroll
            for (int nf = 0; nf < 4; nf++) {
                int nr = wn * 32 + nf * 8 + (lane >> 2);
                bf[nf][0] = sB32[nr * KPAD + col];
                bf[nf][1] = sB32[nr * KPAD + col + 4];
            }
#pragma unroll
            for (int mf = 0; mf < 4; mf++)
#pragma unroll
                for (int nf = 0; nf < 4; nf++)
                    mma_tf32(acc[mf][nf], af[mf], bf[nf]);
        }
        // single sync per iteration is sufficient with 2 stages:
        // the store in iteration i+1 targets stage s^1, last read in
        // iteration i-1, and every thread passed this sync after that.
        __syncthreads();
    }

    // ---- epilogue ----
    float* Cz = C + sC * z;
    const int* cidx = Cidx ? Cidx + (size_t)z * SEQ : nullptr;
#pragma unroll
    for (int mf = 0; mf < 4; mf++) {
#pragma unroll
        for (int half = 0; half < 2; half++) {
            int gm = m0 + wm * 64 + mf * 16 + (lane >> 2) + half * 8;
            if (gm >= Mz) continue;
            int cr = cidx ? cidx[gm] : gm;
            float* crow = Cz + (size_t)cr * ldc;
            const float* rrow = resid ? resid + (size_t)cr * ldc : nullptr;
#pragma unroll
            for (int nf = 0; nf < 4; nf++) {
                int gc = n0 + wn * 32 + nf * 8 + (lane & 3) * 2;
                float2 v;
                v.x = acc[mf][nf][half * 2 + 0];
                v.y = acc[mf][nf][half * 2 + 1];
                if (rrow) { v.x += rrow[gc]; v.y += rrow[gc + 1]; }
                *reinterpret_cast<float2*>(crow + gc) = v;
            }
        }
    }
}

// ---------------------------------------------------------------- aux kernels
__global__ void rmsnorm_k(const float* __restrict__ x, const float* __restrict__ w,
                          float* __restrict__ o)
{
    int t = blockIdx.x, tid = threadIdx.x;
    const float* xr = x + (size_t)t * HDIM;
    float s = 0.f;
    for (int h = tid; h < HDIM; h += 256) { float v = xr[h]; s += v * v; }
    __shared__ float red[256];
    red[tid] = s; __syncthreads();
    for (int st = 128; st > 0; st >>= 1) {
        if (tid < st) red[tid] += red[tid + st];
        __syncthreads();
    }
    float inv = rsqrtf(red[0] / (float)HDIM + 1e-6f);
    float* orow = o + (size_t)t * HDIM;
    for (int h = tid; h < HDIM; h += 256) orow[h] = w[h] * xr[h] * inv;
}

__global__ void rope_inplace_k(float* __restrict__ x, const float* __restrict__ cosb,
                               const float* __restrict__ sinb, int nheads)
{
    int s = blockIdx.x, h = blockIdx.y, d = threadIdx.x;
    float* r = x + ((size_t)s * nheads + h) * HD;
    float v = r[d];
    float w = (d < 64) ? r[d ^ 32] : 0.f;
    __syncthreads();
    if (d < 32)      r[d] = v * cosb[s * RD + d] - w * sinb[s * RD + d];
    else if (d < 64) r[d] = v * cosb[s * RD + d] + w * sinb[s * RD + d];
}

__global__ void softmax_k(float* __restrict__ sc, const float* __restrict__ sink)
{
    int i = blockIdx.x, h = blockIdx.y, tid = threadIdx.x;
    float* row = sc + ((size_t)h * SEQ + i) * (size_t)SEQ;
    const float scale = 0.08838834764831845f;
    __shared__ float red[256];

    float m = -1e30f;
    for (int j = tid; j <= i; j += 256) m = fmaxf(m, row[j] * scale);
    red[tid] = m; __syncthreads();
    for (int st = 128; st > 0; st >>= 1) {
        if (tid < st) red[tid] = fmaxf(red[tid], red[tid + st]);
        __syncthreads();
    }
    m = red[0]; __syncthreads();

    float ssum = 0.f;
    for (int j = tid; j <= i; j += 256) ssum += expf(row[j] * scale - m);
    red[tid] = ssum; __syncthreads();
    for (int st = 128; st > 0; st >>= 1) {
        if (tid < st) red[tid] += red[tid + st];
        __syncthreads();
    }
    float inv = 1.f / (red[0] + expf(sink[h] - m));

    for (int j = tid; j < SEQ; j += 256)
        row[j] = (j <= i) ? expf(row[j] * scale - m) * inv : 0.f;
}

__global__ void zero_cnt_k(int* cnt) { if (threadIdx.x < NE) cnt[threadIdx.x] = 0; }

__global__ void router_k(const float* __restrict__ xf, const float* __restrict__ gw,
                         const float* __restrict__ gbias, int* cnt, int* tok,
                         int* orow, float* wt)
{
    int t = blockIdx.x, tid = threadIdx.x;
    int lane = tid & 31, wid = tid >> 5;
    __shared__ float logits[NE];
    const float* xr = xf + (size_t)t * HDIM;

    for (int e = wid; e < NE; e += 8) {
        const float* gr = gw + (size_t)e * HDIM;
        float p = 0.f;
        for (int hh = lane; hh < HDIM; hh += 32) p += xr[hh] * gr[hh];
        for (int off = 16; off > 0; off >>= 1) p += __shfl_down_sync(0xffffffffu, p, off);
        if (lane == 0) logits[e] = p;
    }
    __syncthreads();

    if (tid == 0) {
        float sg[NE], sfc[NE];
        for (int e = 0; e < NE; e++) {
            sg[e] = 1.f / (1.f + expf(-logits[e]));
            sfc[e] = sg[e] + gbias[e];
        }
        float gs[4];
        for (int g = 0; g < 4; g++) {
            float m1 = -1e30f, m2 = -1e30f;
            for (int j = 0; j < 4; j++) {
                float v = sfc[g * 4 + j];
                if (v > m1) { m2 = m1; m1 = v; } else if (v > m2) m2 = v;
            }
            gs[g] = m1 + m2;
        }
        int g1 = 0;
        for (int g = 1; g < 4; g++) if (gs[g] > gs[g1]) g1 = g;
        int g2 = -1;
        for (int g = 0; g < 4; g++) {
            if (g == g1) continue;
            if (g2 < 0 || gs[g] > gs[g2]) g2 = g;
        }
        bool allow[NE];
        for (int e = 0; e < NE; e++) { int g = e >> 2; allow[e] = (g == g1 || g == g2); }

        int idx[TKN]; float tws[TKN]; float sum = 0.f;
        bool used[NE] = {};
        for (int j = 0; j < TKN; j++) {
            int bi = -1; float bv = -1e30f;
            for (int e = 0; e < NE; e++)
                if (allow[e] && !used[e] && sfc[e] > bv) { bv = sfc[e]; bi = e; }
            used[bi] = true; idx[j] = bi; tws[j] = sg[bi]; sum += tws[j];
        }
        float invs = 2.5f / (sum + 1e-20f);
        for (int j = 0; j < TKN; j++) {
            int e = idx[j];
            int pos = atomicAdd(&cnt[e], 1);
            tok[e * SEQ + pos]  = t;
            orow[e * SEQ + pos] = j * SEQ + t;
            wt[e * SEQ + pos]   = tws[j] * invs;
        }
    }
}

__global__ void silu_k(float* __restrict__ gbuf, const float* __restrict__ ubuf,
                       const float* __restrict__ wt, const int* __restrict__ cnt)
{
    int e = blockIdx.y, r = blockIdx.x;
    if (r >= cnt[e]) return;
    float w = wt[e * SEQ + r];
    size_t base = ((size_t)e * SEQ + r) * FF;
    for (int f = threadIdx.x; f < FF; f += 256) {
        float gv = gbuf[base + f], uv = ubuf[base + f];
        float sig = 1.f / (1.f + expf(-gv));
        gbuf[base + f] = gv * sig * uv * w;
    }
}

__global__ void final_k(const float* __restrict__ h1, const float* __restrict__ slot,
                        float* __restrict__ out)
{
    size_t i = (size_t)blockIdx.x * 256 + threadIdx.x;
    const size_t NTOT = (size_t)SEQ * HDIM;
    out[i] = h1[i] + slot[i] + slot[NTOT + i] + slot[2 * NTOT + i] + slot[3 * NTOT + i];
}

// ---------------------------------------------------------------- launch
extern "C" void kernel_launch(void* const* d_in, const int* in_sizes, int n_in,
                              void* d_out, int out_size)
{
    const float* x      = (const float*)d_in[0];
    const float* cosb   = (const float*)d_in[1];
    const float* sinb   = (const float*)d_in[2];
    const float* ln1    = (const float*)d_in[3];
    const float* ln2    = (const float*)d_in[4];
    const float* Wq     = (const float*)d_in[5];
    const float* Wk     = (const float*)d_in[6];
    const float* Wv     = (const float*)d_in[7];
    const float* Wo     = (const float*)d_in[8];
    const float* sink   = (const float*)d_in[9];
    const float* gate_w = (const float*)d_in[10];
    const float* gate_b = (const float*)d_in[11];
    const float* Weg    = (const float*)d_in[12];
    const float* Weu    = (const float*)d_in[13];
    const float* Wed    = (const float*)d_in[14];
    float* out = (float*)d_out;

    cudaFuncSetAttribute(tgemm_k<true>,  cudaFuncAttributeMaxDynamicSharedMemorySize, DSMEM_BYTES);
    cudaFuncSetAttribute(tgemm_k<false>, cudaFuncAttributeMaxDynamicSharedMemorySize, DSMEM_BYTES);

    void *p_xn, *p_qraw, *p_kraw, *p_vraw, *p_sc, *p_ao, *p_h1, *p_xf,
         *p_gb, *p_ub, *p_slot, *p_cnt, *p_tok, *p_orow, *p_wt;
    cudaGetSymbolAddress(&p_xn, g_xn);
    cudaGetSymbolAddress(&p_qraw, g_qraw);
    cudaGetSymbolAddress(&p_kraw, g_kraw);
    cudaGetSymbolAddress(&p_vraw, g_vraw);
    cudaGetSymbolAddress(&p_sc, g_scores);
    cudaGetSymbolAddress(&p_ao, g_ao);
    cudaGetSymbolAddress(&p_h1, g_h1);
    cudaGetSymbolAddress(&p_xf, g_xf);
    cudaGetSymbolAddress(&p_gb, g_gbuf);
    cudaGetSymbolAddress(&p_ub, g_ubuf);
    cudaGetSymbolAddress(&p_slot, g_slot);
    cudaGetSymbolAddress(&p_cnt, g_cnt);
    cudaGetSymbolAddress(&p_tok, g_tok);
    cudaGetSymbolAddress(&p_orow, g_orow);
    cudaGetSymbolAddress(&p_wt, g_wt);

    float* xn   = (float*)p_xn;
    float* qraw = (float*)p_qraw;  float* kraw = (float*)p_kraw;  float* vraw = (float*)p_vraw;
    float* sc   = (float*)p_sc;    float* ao   = (float*)p_ao;    float* h1   = (float*)p_h1;
    float* xf   = (float*)p_xf;    float* gb   = (float*)p_gb;    float* ub   = (float*)p_ub;
    float* slot = (float*)p_slot;
    int* cnt = (int*)p_cnt; int* tok = (int*)p_tok; int* orow = (int*)p_orow;
    float* wt = (float*)p_wt;

    zero_cnt_k<<<1, 32>>>(cnt);
    rmsnorm_k<<<SEQ, 256>>>(x, ln1, xn);

    // QKV projections (tf32 mma.sync)
    tgemm_k<false><<<dim3(HDIM / TN, SEQ / TM, 1), 256, DSMEM_BYTES>>>(
        xn, Wq, qraw, nullptr, SEQ, HDIM, HDIM, HDIM, HDIM, HDIM,
        0, 0, 0, 1, nullptr, nullptr, nullptr, 0, 0);
    tgemm_k<false><<<dim3(512 / TN, SEQ / TM, 1), 256, DSMEM_BYTES>>>(
        xn, Wk, kraw, nullptr, SEQ, 512, HDIM, HDIM, 512, 512,
        0, 0, 0, 1, nullptr, nullptr, nullptr, 0, 0);
    tgemm_k<false><<<dim3(512 / TN, SEQ / TM, 1), 256, DSMEM_BYTES>>>(
        xn, Wv, vraw, nullptr, SEQ, 512, HDIM, HDIM, 512, 512,
        0, 0, 0, 1, nullptr, nullptr, nullptr, 0, 0);

    // RoPE in place
    rope_inplace_k<<<dim3(SEQ, NH), 128>>>(qraw, cosb, sinb, NH);
    rope_inplace_k<<<dim3(SEQ, NKV), 128>>>(kraw, cosb, sinb, NKV);

    // scores[h] = q[h] @ k[h/4]^T  (causal tile skip)
    tgemm_k<true><<<dim3(SEQ / TN, SEQ / TM, NH), 256, DSMEM_BYTES>>>(
        qraw, kraw, sc, nullptr, SEQ, SEQ, HD, NH * HD, NKV * HD, SEQ,
        128, 128, (long long)SEQ * SEQ, NH / NKV,
        nullptr, nullptr, nullptr, 1, 0);

    softmax_k<<<dim3(SEQ, NH), 256>>>(sc, sink);

    // ao[:, h*128:(h+1)*128] = probs[h] @ v[h/4]  (K capped causally)
    tgemm_k<false><<<dim3(1, SEQ / TM, NH), 256, DSMEM_BYTES>>>(
        sc, vraw, ao, nullptr, SEQ, HD, SEQ, SEQ, NKV * HD, HDIM,
        (long long)SEQ * SEQ, 128, 128, NH / NKV,
        nullptr, nullptr, nullptr, 0, 1);

    // h1 = ao @ Wo + x
    tgemm_k<false><<<dim3(HDIM / TN, SEQ / TM, 1), 256, DSMEM_BYTES>>>(
        ao, Wo, h1, x, SEQ, HDIM, HDIM, HDIM, HDIM, HDIM,
        0, 0, 0, 1, nullptr, nullptr, nullptr, 0, 0);

    rmsnorm_k<<<SEQ, 256>>>(h1, ln2, xf);
    router_k<<<SEQ, 256>>>(xf, gate_w, gate_b, cnt, tok, orow, wt);

    // expert gate / up projections (row-gathered A)
    tgemm_k<false><<<dim3(FF / TN, SEQ / TM, NE), 256, DSMEM_BYTES>>>(
        xf, Weg, gb, nullptr, SEQ, FF, HDIM, HDIM, FF, FF,
        0, (long long)HDIM * FF, (long long)SEQ * FF, 1, tok, nullptr, cnt, 0, 0);
    tgemm_k<false><<<dim3(FF / TN, SEQ / TM, NE), 256, DSMEM_BYTES>>>(
        xf, Weu, ub, nullptr, SEQ, FF, HDIM, HDIM, FF, FF,
        0, (long long)HDIM * FF, (long long)SEQ * FF, 1, tok, nullptr, cnt, 0, 0);

    silu_k<<<dim3(SEQ, NE), 256>>>(gb, ub, wt, cnt);

    // down projection, scattered to per-(slot,token) rows
    tgemm_k<false><<<dim3(HDIM / TN, SEQ / TM, NE), 256, DSMEM_BYTES>>>(
        gb, Wed, slot, nullptr, SEQ, HDIM, FF, FF, HDIM, HDIM,
        (long long)SEQ * FF, (long long)FF * HDIM, 0, 1, nullptr, orow, cnt, 0, 0);

    final_k<<<(SEQ * HDIM) / 256, 256>>>(h1, slot, out);
}

// round 6
// speedup vs baseline: 3.4154x; 1.7374x over previous
#include <cuda_runtime.h>
#include <math.h>
#include <stdint.h>

#define SEQ 2048
#define HDIM 2048
#define NH 16
#define NKV 4
#define HD 128
#define RD 64
#define NE 16
#define FF 512
#define TKN 4

#define QKVW 3072            // fused q|k|v width
#define GUW 1024             // fused gate|up width

#define NSTG 3
#define STG_FLOATS 8192      // A(4096) + B(4096) per stage
#define DSMEM_BYTES (NSTG * STG_FLOATS * 4)   // 98304

// ---------------------------------------------------------------- helpers
static __device__ __forceinline__ uint32_t smem_u32(const void* p) {
    uint32_t a;
    asm("{ .reg .u64 t; cvta.to.shared.u64 t, %1; cvt.u32.u64 %0, t; }"
        : "=r"(a) : "l"(p));
    return a;
}
static __device__ __forceinline__ uint32_t f2tf(float f) {
    uint32_t u; asm("cvt.rna.tf32.f32 %0, %1;" : "=r"(u) : "f"(f)); return u;
}
static __device__ __forceinline__ float f2tf_f(float f) {
    return __uint_as_float(f2tf(f));
}

static __device__ __forceinline__ void mma_tf32(
    float* c, const uint32_t* a, const uint32_t* b)
{
    asm volatile(
        "mma.sync.aligned.m16n8k8.row.col.f32.tf32.tf32.f32 "
        "{%0,%1,%2,%3}, {%4,%5,%6,%7}, {%8,%9}, {%0,%1,%2,%3};"
        : "+f"(c[0]), "+f"(c[1]), "+f"(c[2]), "+f"(c[3])
        : "r"(a[0]), "r"(a[1]), "r"(a[2]), "r"(a[3]), "r"(b[0]), "r"(b[1]));
}

static __device__ __forceinline__ void cp16(uint32_t dst, const float* src, uint32_t sz) {
    asm volatile("cp.async.cg.shared.global [%0], [%1], 16, %2;"
                 :: "r"(dst), "l"(src), "r"(sz));
}
#define CP_COMMIT() asm volatile("cp.async.commit_group;" ::: "memory")
#define CP_WAIT1()  asm volatile("cp.async.wait_group 1;" ::: "memory")

// ---------------------------------------------------------------- scratch
__device__ float g_xn[SEQ * HDIM];
__device__ float g_qkv[SEQ * QKVW];
__device__ float g_vT[512 * SEQ];
__device__ float g_wqkvT[QKVW * HDIM];
__device__ float g_woT[HDIM * HDIM];
__device__ float g_scores[(size_t)NH * SEQ * SEQ];
__device__ float g_ao[SEQ * HDIM];
__device__ float g_h1[SEQ * HDIM];
__device__ float g_xf[SEQ * HDIM];
__device__ float g_wguT[NE * GUW * HDIM];
__device__ float g_wedT[NE * HDIM * FF];
__device__ float g_gu[(size_t)NE * SEQ * GUW];
__device__ float g_hb[NE * SEQ * FF];
__device__ float g_slot[TKN * SEQ * HDIM];
__device__ int   g_cnt[NE];
__device__ int   g_tok[NE * SEQ];
__device__ int   g_orow[NE * SEQ];
__device__ float g_wt[NE * SEQ];

// ---------------------------------------------------------------- tf32 GEMM
// C[M,N] = A[M,K] @ B[N,K]^T (+resid). All operands pre-rounded to tf32.
// A rows K-contiguous (lda), B rows K-contiguous (ldb).
// Batched over z: A += sA*z, B += sB*(z/bzdiv), C += sC*z.
// Aidx: per-z row gather for A; Cidx: per-z row scatter for C; cnt: M override.
// causal: skip tiles with n0 > m0+127. kcausal: cap K at m0+128.
// roundC: round output to tf32 (when C feeds another GEMM as an operand).
__global__ void __launch_bounds__(256, 2) tgemm_k(
    const float* __restrict__ A, const float* __restrict__ B,
    float* __restrict__ C, const float* __restrict__ resid,
    int M, int N, int K, int lda, int ldb, int ldc,
    long long sA, long long sB, long long sC, int bzdiv,
    const int* __restrict__ Aidx, const int* __restrict__ Cidx,
    const int* __restrict__ cnt, int causal, int kcausal, int roundC)
{
    int z = blockIdx.z;
    int Mz = cnt ? cnt[z] : M;
    int m0 = blockIdx.y * 128, n0 = blockIdx.x * 128;
    if (m0 >= Mz) return;
    if (causal && n0 > m0 + 127) return;
    int Keff = kcausal ? min(K, m0 + 128) : K;
    int nch = Keff >> 5;

    extern __shared__ float dsm[];
    uint32_t sb = smem_u32(dsm);

    int tid = threadIdx.x, lane = tid & 31, wid = tid >> 5;
    int wm = wid & 1, wn = wid >> 1;

    const float* Az = A + sA * z;
    const float* Bz = B + sB * (z / bzdiv);
    const int* aidx = Aidx ? Aidx + (size_t)z * SEQ : nullptr;

    // copy map: thread -> (row am, granules g0..g0+3)  [granule = 16B = 4 floats]
    int am = tid >> 1;
    int g0 = (tid & 1) * 4;
    const float* asrc; uint32_t avalid;
    {
        int gm = m0 + am;
        if (gm < Mz) {
            int ar = aidx ? aidx[gm] : gm;
            asrc = Az + (size_t)ar * lda + g0 * 4;
            avalid = 16u;
        } else { asrc = Az; avalid = 0u; }
    }
    const float* bsrc = Bz + (size_t)(n0 + am) * ldb + g0 * 4;
    uint32_t arow7 = (uint32_t)(am & 7);
    uint32_t abyte = (uint32_t)am << 7;   // row * 128B

    float acc[4][4][4];
#pragma unroll
    for (int mf = 0; mf < 4; mf++)
#pragma unroll
        for (int nf = 0; nf < 4; nf++)
#pragma unroll
            for (int r = 0; r < 4; r++) acc[mf][nf][r] = 0.f;

    // prologue: stages 0,1
#pragma unroll
    for (int p = 0; p < 2; p++) {
        if (p < nch) {
            uint32_t stg = sb + (uint32_t)p * (STG_FLOATS * 4);
            const float* as = asrc + p * 32;
            const float* bs = bsrc + p * 32;
#pragma unroll
            for (int j = 0; j < 4; j++) {
                uint32_t sw = (uint32_t)(((g0 + j) ^ arow7) << 4);
                cp16(stg + abyte + sw, as + 4 * j, avalid);
                cp16(stg + 16384u + abyte + sw, bs + 4 * j, 16u);
            }
            CP_COMMIT();
        }
    }

    int c4 = lane & 3;
    int rowA[4], rowB[4];
#pragma unroll
    for (int mf = 0; mf < 4; mf++) rowA[mf] = wm * 64 + mf * 16 + (lane >> 2);
#pragma unroll
    for (int nf = 0; nf < 4; nf++) rowB[nf] = wn * 32 + nf * 8 + (lane >> 2);

    for (int i = 0; i < nch; i++) {
        CP_WAIT1();
        __syncthreads();

        // issue chunk i+2 into stage (i+2)%3 (consumed at iteration i-1)
        if (i + 2 < nch) {
            uint32_t stg = sb + (uint32_t)((i + 2) % NSTG) * (STG_FLOATS * 4);
            const float* as = asrc + (i + 2) * 32;
            const float* bs = bsrc + (i + 2) * 32;
#pragma unroll
            for (int j = 0; j < 4; j++) {
                uint32_t sw = (uint32_t)(((g0 + j) ^ arow7) << 4);
                cp16(stg + abyte + sw, as + 4 * j, avalid);
                cp16(stg + 16384u + abyte + sw, bs + 4 * j, 16u);
            }
            CP_COMMIT();
        }

        const uint32_t* sA32 = reinterpret_cast<const uint32_t*>(dsm + (i % NSTG) * STG_FLOATS);
        const uint32_t* sB32 = sA32 + 4096;

#pragma unroll
        for (int ks = 0; ks < 4; ks++) {
            int g = ks * 2;
            uint32_t af[4][4], bf[4][2];
#pragma unroll
            for (int mf = 0; mf < 4; mf++) {
                int r = rowA[mf], r8 = r + 8;
                af[mf][0] = sA32[(r  << 5) + (((g    ) ^ (r  & 7)) << 2) + c4];
                af[mf][1] = sA32[(r8 << 5) + (((g    ) ^ (r8 & 7)) << 2) + c4];
                af[mf][2] = sA32[(r  << 5) + (((g + 1) ^ (r  & 7)) << 2) + c4];
                af[mf][3] = sA32[(r8 << 5) + (((g + 1) ^ (r8 & 7)) << 2) + c4];
            }
#pragma unroll
            for (int nf = 0; nf < 4; nf++) {
                int r = rowB[nf];
                bf[nf][0] = sB32[(r << 5) + (((g    ) ^ (r & 7)) << 2) + c4];
                bf[nf][1] = sB32[(r << 5) + (((g + 1) ^ (r & 7)) << 2) + c4];
            }
#pragma unroll
            for (int mf = 0; mf < 4; mf++)
#pragma unroll
                for (int nf = 0; nf < 4; nf++)
                    mma_tf32(acc[mf][nf], af[mf], bf[nf]);
        }
    }

    // ---- epilogue ----
    float* Cz = C + sC * z;
    const int* cidx = Cidx ? Cidx + (size_t)z * SEQ : nullptr;
#pragma unroll
    for (int mf = 0; mf < 4; mf++) {
#pragma unroll
        for (int half = 0; half < 2; half++) {
            int gm = m0 + wm * 64 + mf * 16 + (lane >> 2) + half * 8;
            if (gm >= Mz) continue;
            int cr = cidx ? cidx[gm] : gm;
            float* crow = Cz + (size_t)cr * ldc;
            const float* rrow = resid ? resid + (size_t)cr * ldc : nullptr;
#pragma unroll
            for (int nf = 0; nf < 4; nf++) {
                int gc = n0 + wn * 32 + nf * 8 + (lane & 3) * 2;
                float2 v;
                v.x = acc[mf][nf][half * 2 + 0];
                v.y = acc[mf][nf][half * 2 + 1];
                if (rrow) { v.x += rrow[gc]; v.y += rrow[gc + 1]; }
                if (roundC) { v.x = f2tf_f(v.x); v.y = f2tf_f(v.y); }
                *reinterpret_cast<float2*>(crow + gc) = v;
            }
        }
    }
}

// ---------------------------------------------------------------- transpose
// out[z][c][r] = round_tf32(in[z][r][c]); in row stride ldin, out row stride ldout.
__global__ void transpose_k(const float* __restrict__ in, float* __restrict__ out,
                            int R, int C, int ldin, int ldout,
                            long long szin, long long szout)
{
    __shared__ float t[32][33];
    int z = blockIdx.z;
    const float* inz = in + szin * z;
    float* outz = out + szout * z;
    int r0 = blockIdx.y * 32, c0 = blockIdx.x * 32;
    int tx = threadIdx.x & 31, ty = threadIdx.x >> 5;
#pragma unroll
    for (int dy = 0; dy < 32; dy += 8) {
        int r = r0 + ty + dy, c = c0 + tx;
        t[ty + dy][tx] = (r < R && c < C) ? inz[(size_t)r * ldin + c] : 0.f;
    }
    __syncthreads();
#pragma unroll
    for (int dy = 0; dy < 32; dy += 8) {
        int c = c0 + ty + dy, r = r0 + tx;
        if (c < C && r < R)
            outz[(size_t)c * ldout + r] = f2tf_f(t[tx][ty + dy]);
    }
}

// ---------------------------------------------------------------- aux kernels
// o      : tf32-rounded output (GEMM A operand)
// ofull  : optional unrounded fp32 output (router input)
__global__ void rmsnorm_k(const float* __restrict__ x, const float* __restrict__ w,
                          float* __restrict__ o, float* __restrict__ ofull)
{
    int t = blockIdx.x, tid = threadIdx.x;
    const float* xr = x + (size_t)t * HDIM;
    float s = 0.f;
    for (int h = tid; h < HDIM; h += 256) { float v = xr[h]; s += v * v; }
    __shared__ float red[256];
    red[tid] = s; __syncthreads();
    for (int st = 128; st > 0; st >>= 1) {
        if (tid < st) red[tid] += red[tid + st];
        __syncthreads();
    }
    float inv = rsqrtf(red[0] / (float)HDIM + 1e-6f);
    float* orow = o + (size_t)t * HDIM;
    float* frow = ofull ? ofull + (size_t)t * HDIM : nullptr;
    for (int h = tid; h < HDIM; h += 256) {
        float v = w[h] * xr[h] * inv;
        orow[h] = f2tf_f(v);
        if (frow) frow[h] = v;
    }
}

__global__ void rope_qkv_k(float* __restrict__ qkv, const float* __restrict__ cosb,
                           const float* __restrict__ sinb)
{
    int s = blockIdx.x, y = blockIdx.y, d = threadIdx.x;
    int col = (y < NH) ? y * HD : 2048 + (y - NH) * HD;
    float* r = qkv + (size_t)s * QKVW + col;
    float v = r[d];
    float w = (d < 64) ? r[d ^ 32] : 0.f;
    __syncthreads();
    if (d < 32)      r[d] = f2tf_f(v * cosb[s * RD + d] - w * sinb[s * RD + d]);
    else if (d < 64) r[d] = f2tf_f(v * cosb[s * RD + d] + w * sinb[s * RD + d]);
}

__global__ void softmax_k(float* __restrict__ sc, const float* __restrict__ sink)
{
    int i = blockIdx.x, h = blockIdx.y, tid = threadIdx.x;
    float* row = sc + ((size_t)h * SEQ + i) * (size_t)SEQ;
    const float scale = 0.08838834764831845f;
    __shared__ float red[256];

    float m = -1e30f;
    for (int j = tid; j <= i; j += 256) m = fmaxf(m, row[j] * scale);
    red[tid] = m; __syncthreads();
    for (int st = 128; st > 0; st >>= 1) {
        if (tid < st) red[tid] = fmaxf(red[tid], red[tid + st]);
        __syncthreads();
    }
    m = red[0]; __syncthreads();

    float ssum = 0.f;
    for (int j = tid; j <= i; j += 256) ssum += expf(row[j] * scale - m);
    red[tid] = ssum; __syncthreads();
    for (int st = 128; st > 0; st >>= 1) {
        if (tid < st) red[tid] += red[tid + st];
        __syncthreads();
    }
    float inv = 1.f / (red[0] + expf(sink[h] - m));

    for (int j = tid; j < SEQ; j += 256)
        row[j] = (j <= i) ? f2tf_f(expf(row[j] * scale - m) * inv) : 0.f;
}

__global__ void zero_cnt_k(int* cnt) { if (threadIdx.x < NE) cnt[threadIdx.x] = 0; }

__global__ void router_k(const float* __restrict__ xf, const float* __restrict__ gw,
                         const float* __restrict__ gbias, int* cnt, int* tok,
                         int* orow, float* wt)
{
    int t = blockIdx.x, tid = threadIdx.x;
    int lane = tid & 31, wid = tid >> 5;
    __shared__ float logits[NE];
    const float* xr = xf + (size_t)t * HDIM;

    for (int e = wid; e < NE; e += 8) {
        const float* gr = gw + (size_t)e * HDIM;
        float p = 0.f;
        for (int hh = lane; hh < HDIM; hh += 32) p += xr[hh] * gr[hh];
        for (int off = 16; off > 0; off >>= 1) p += __shfl_down_sync(0xffffffffu, p, off);
        if (lane == 0) logits[e] = p;
    }
    __syncthreads();

    if (tid == 0) {
        float sg[NE], sfc[NE];
        for (int e = 0; e < NE; e++) {
            sg[e] = 1.f / (1.f + expf(-logits[e]));
            sfc[e] = sg[e] + gbias[e];
        }
        float gs[4];
        for (int g = 0; g < 4; g++) {
            float m1 = -1e30f, m2 = -1e30f;
            for (int j = 0; j < 4; j++) {
                float v = sfc[g * 4 + j];
                if (v > m1) { m2 = m1; m1 = v; } else if (v > m2) m2 = v;
            }
            gs[g] = m1 + m2;
        }
        int g1 = 0;
        for (int g = 1; g < 4; g++) if (gs[g] > gs[g1]) g1 = g;
        int g2 = -1;
        for (int g = 0; g < 4; g++) {
            if (g == g1) continue;
            if (g2 < 0 || gs[g] > gs[g2]) g2 = g;
        }
        bool allow[NE];
        for (int e = 0; e < NE; e++) { int g = e >> 2; allow[e] = (g == g1 || g == g2); }

        int idx[TKN]; float tws[TKN]; float sum = 0.f;
        bool used[NE] = {};
        for (int j = 0; j < TKN; j++) {
            int bi = -1; float bv = -1e30f;
            for (int e = 0; e < NE; e++)
                if (allow[e] && !used[e] && sfc[e] > bv) { bv = sfc[e]; bi = e; }
            used[bi] = true; idx[j] = bi; tws[j] = sg[bi]; sum += tws[j];
        }
        float invs = 2.5f / (sum + 1e-20f);
        for (int j = 0; j < TKN; j++) {
            int e = idx[j];
            int pos = atomicAdd(&cnt[e], 1);
            tok[e * SEQ + pos]  = t;
            orow[e * SEQ + pos] = j * SEQ + t;
            wt[e * SEQ + pos]   = tws[j] * invs;
        }
    }
}

__global__ void silu_k(const float* __restrict__ gu, float* __restrict__ hb,
                       const float* __restrict__ wt, const int* __restrict__ cnt)
{
    int e = blockIdx.y, r = blockIdx.x;
    if (r >= cnt[e]) return;
    float w = wt[e * SEQ + r];
    const float* g = gu + ((size_t)e * SEQ + r) * GUW;
    float* o = hb + ((size_t)e * SEQ + r) * FF;
    for (int f = threadIdx.x; f < FF; f += 256) {
        float gv = g[f], uv = g[FF + f];
        float sig = 1.f / (1.f + expf(-gv));
        o[f] = f2tf_f(gv * sig * uv * w);
    }
}

__global__ void final_k(const float* __restrict__ h1, const float* __restrict__ slot,
                        float* __restrict__ out)
{
    size_t i = (size_t)blockIdx.x * 256 + threadIdx.x;
    const size_t NTOT = (size_t)SEQ * HDIM;
    out[i] = h1[i] + slot[i] + slot[NTOT + i] + slot[2 * NTOT + i] + slot[3 * NTOT + i];
}

// ---------------------------------------------------------------- launch
extern "C" void kernel_launch(void* const* d_in, const int* in_sizes, int n_in,
                              void* d_out, int out_size)
{
    const float* x      = (const float*)d_in[0];
    const float* cosb   = (const float*)d_in[1];
    const float* sinb   = (const float*)d_in[2];
    const float* ln1    = (const float*)d_in[3];
    const float* ln2    = (const float*)d_in[4];
    const float* Wq     = (const float*)d_in[5];
    const float* Wk     = (const float*)d_in[6];
    const float* Wv     = (const float*)d_in[7];
    const float* Wo     = (const float*)d_in[8];
    const float* sink   = (const float*)d_in[9];
    const float* gate_w = (const float*)d_in[10];
    const float* gate_b = (const float*)d_in[11];
    const float* Weg    = (const float*)d_in[12];
    const float* Weu    = (const float*)d_in[13];
    const float* Wed    = (const float*)d_in[14];
    float* out = (float*)d_out;

    cudaFuncSetAttribute(tgemm_k, cudaFuncAttributeMaxDynamicSharedMemorySize, DSMEM_BYTES);

    void *p_xn, *p_qkv, *p_vT, *p_wqkvT, *p_woT, *p_sc, *p_ao, *p_h1, *p_xf,
         *p_wguT, *p_wedT, *p_gu, *p_hb, *p_slot, *p_cnt, *p_tok, *p_orow, *p_wt;
    cudaGetSymbolAddress(&p_xn, g_xn);
    cudaGetSymbolAddress(&p_qkv, g_qkv);
    cudaGetSymbolAddress(&p_vT, g_vT);
    cudaGetSymbolAddress(&p_wqkvT, g_wqkvT);
    cudaGetSymbolAddress(&p_woT, g_woT);
    cudaGetSymbolAddress(&p_sc, g_scores);
    cudaGetSymbolAddress(&p_ao, g_ao);
    cudaGetSymbolAddress(&p_h1, g_h1);
    cudaGetSymbolAddress(&p_xf, g_xf);
    cudaGetSymbolAddress(&p_wguT, g_wguT);
    cudaGetSymbolAddress(&p_wedT, g_wedT);
    cudaGetSymbolAddress(&p_gu, g_gu);
    cudaGetSymbolAddress(&p_hb, g_hb);
    cudaGetSymbolAddress(&p_slot, g_slot);
    cudaGetSymbolAddress(&p_cnt, g_cnt);
    cudaGetSymbolAddress(&p_tok, g_tok);
    cudaGetSymbolAddress(&p_orow, g_orow);
    cudaGetSymbolAddress(&p_wt, g_wt);

    float* xn    = (float*)p_xn;
    float* qkv   = (float*)p_qkv;
    float* vT    = (float*)p_vT;
    float* wqkvT = (float*)p_wqkvT;
    float* woT   = (float*)p_woT;
    float* sc    = (float*)p_sc;
    float* ao    = (float*)p_ao;
    float* h1    = (float*)p_h1;
    float* xf    = (float*)p_xf;
    float* wguT  = (float*)p_wguT;
    float* wedT  = (float*)p_wedT;
    float* gu    = (float*)p_gu;
    float* hb    = (float*)p_hb;
    float* slot  = (float*)p_slot;
    int* cnt = (int*)p_cnt; int* tok = (int*)p_tok; int* orow = (int*)p_orow;
    float* wt = (float*)p_wt;

    zero_cnt_k<<<1, 32>>>(cnt);

    // --- weight transposes + tf32 rounding (inputs only; deterministic) ---
    transpose_k<<<dim3(64, 64, 1), 256>>>(Wq, wqkvT, HDIM, 2048, 2048, HDIM, 0, 0);
    transpose_k<<<dim3(16, 64, 1), 256>>>(Wk, wqkvT + (size_t)2048 * HDIM, HDIM, 512, 512, HDIM, 0, 0);
    transpose_k<<<dim3(16, 64, 1), 256>>>(Wv, wqkvT + (size_t)2560 * HDIM, HDIM, 512, 512, HDIM, 0, 0);
    transpose_k<<<dim3(64, 64, 1), 256>>>(Wo, woT, HDIM, HDIM, HDIM, HDIM, 0, 0);
    transpose_k<<<dim3(16, 64, NE), 256>>>(Weg, wguT, HDIM, FF, FF, HDIM,
        (long long)HDIM * FF, (long long)GUW * HDIM);
    transpose_k<<<dim3(16, 64, NE), 256>>>(Weu, wguT + (size_t)FF * HDIM, HDIM, FF, FF, HDIM,
        (long long)HDIM * FF, (long long)GUW * HDIM);
    transpose_k<<<dim3(64, 16, NE), 256>>>(Wed, wedT, FF, HDIM, HDIM, FF,
        (long long)FF * HDIM, (long long)HDIM * FF);

    rmsnorm_k<<<SEQ, 256>>>(x, ln1, xn, nullptr);

    // fused QKV: qkv[s][0:2048]=q, [2048:2560]=k, [2560:3072]=v
    tgemm_k<<<dim3(QKVW / 128, SEQ / 128, 1), 256, DSMEM_BYTES>>>(
        xn, wqkvT, qkv, nullptr, SEQ, QKVW, HDIM, HDIM, HDIM, QKVW,
        0, 0, 0, 1, nullptr, nullptr, nullptr, 0, 0, 1);

    rope_qkv_k<<<dim3(SEQ, NH + NKV), 128>>>(qkv, cosb, sinb);

    // vT[d][s] from qkv cols 2560..3071
    transpose_k<<<dim3(16, 64, 1), 256>>>(qkv + 2560, vT, SEQ, 512, QKVW, SEQ, 0, 0);

    // scores[h] = q[h] @ k[h/4]^T
    tgemm_k<<<dim3(SEQ / 128, SEQ / 128, NH), 256, DSMEM_BYTES>>>(
        qkv, qkv + 2048, sc, nullptr, SEQ, SEQ, HD, QKVW, QKVW, SEQ,
        128, 128, (long long)SEQ * SEQ, NH / NKV,
        nullptr, nullptr, nullptr, 1, 0, 0);

    softmax_k<<<dim3(SEQ, NH), 256>>>(sc, sink);

    // ao[:, h*128:(h+1)*128] = probs[h] @ vT[h/4]^T  (K capped causally)
    tgemm_k<<<dim3(1, SEQ / 128, NH), 256, DSMEM_BYTES>>>(
        sc, vT, ao, nullptr, SEQ, HD, SEQ, SEQ, SEQ, HDIM,
        (long long)SEQ * SEQ, (long long)HD * SEQ, 128, NH / NKV,
        nullptr, nullptr, nullptr, 0, 1, 1);

    // h1 = ao @ Wo + x
    tgemm_k<<<dim3(HDIM / 128, SEQ / 128, 1), 256, DSMEM_BYTES>>>(
        ao, woT, h1, x, SEQ, HDIM, HDIM, HDIM, HDIM, HDIM,
        0, 0, 0, 1, nullptr, nullptr, nullptr, 0, 0, 0);

    // xf (tf32, for GEMM) + xn reused as unrounded copy (for router)
    rmsnorm_k<<<SEQ, 256>>>(h1, ln2, xf, xn);
    router_k<<<SEQ, 256>>>(xn, gate_w, gate_b, cnt, tok, orow, wt);

    // fused gate|up per expert (row-gathered A)
    tgemm_k<<<dim3(GUW / 128, SEQ / 128, NE), 256, DSMEM_BYTES>>>(
        xf, wguT, gu, nullptr, SEQ, GUW, HDIM, HDIM, HDIM, GUW,
        0, (long long)GUW * HDIM, (long long)SEQ * GUW, 1,
        tok, nullptr, cnt, 0, 0, 0);

    silu_k<<<dim3(SEQ, NE), 256>>>(gu, hb, wt, cnt);

    // down projection, scattered to per-(slot,token) rows
    tgemm_k<<<dim3(HDIM / 128, SEQ / 128, NE), 256, DSMEM_BYTES>>>(
        hb, wedT, slot, nullptr, SEQ, HDIM, FF, FF, FF, HDIM,
        (long long)SEQ * FF, (long long)HDIM * FF, 0, 1,
        nullptr, orow, cnt, 0, 0, 0);

    final_k<<<(SEQ * HDIM) / 256, 256>>>(h1, slot, out);
}

// round 11
// speedup vs baseline: 3.9397x; 1.1535x over previous
#include <cuda_runtime.h>
#include <math.h>
#include <stdint.h>

#define SEQ 2048
#define HDIM 2048
#define NH 16
#define NKV 4
#define HD 128
#define RD 64
#define NE 16
#define FF 512
#define TKN 4
#define GUW 1024

#define NSTG 3
#define STG_FLOATS 8192
#define DSMEM_BYTES (NSTG * STG_FLOATS * 4)   // 98304

// weight scratch offsets (floats)
#define WQ_OFF  0
#define WK_OFF  4194304
#define WV_OFF  5242880
#define WO_OFF  6291456
#define WEG_OFF 10485760
#define WEU_OFF 27262976
#define WED_OFF 44040192
#define WR_TOT  60817408

// ---------------------------------------------------------------- helpers
static __device__ __forceinline__ uint32_t smem_u32(const void* p) {
    uint32_t a;
    asm("{ .reg .u64 t; cvta.to.shared.u64 t, %1; cvt.u32.u64 %0, t; }"
        : "=r"(a) : "l"(p));
    return a;
}
static __device__ __forceinline__ uint32_t f2tf(float f) {
    uint32_t u; asm("cvt.rna.tf32.f32 %0, %1;" : "=r"(u) : "f"(f)); return u;
}
static __device__ __forceinline__ float f2tf_f(float f) {
    return __uint_as_float(f2tf(f));
}

static __device__ __forceinline__ void mma_tf32(
    float* c, const uint32_t* a, const uint32_t* b)
{
    asm volatile(
        "mma.sync.aligned.m16n8k8.row.col.f32.tf32.tf32.f32 "
        "{%0,%1,%2,%3}, {%4,%5,%6,%7}, {%8,%9}, {%0,%1,%2,%3};"
        : "+f"(c[0]), "+f"(c[1]), "+f"(c[2]), "+f"(c[3])
        : "r"(a[0]), "r"(a[1]), "r"(a[2]), "r"(a[3]), "r"(b[0]), "r"(b[1]));
}

static __device__ __forceinline__ void cp16(uint32_t dst, const float* src, uint32_t sz) {
    asm volatile("cp.async.cg.shared.global [%0], [%1], 16, %2;"
                 :: "r"(dst), "l"(src), "r"(sz));
}
#define CP_COMMIT() asm volatile("cp.async.commit_group;" ::: "memory")
#define CP_WAIT1()  asm volatile("cp.async.wait_group 1;" ::: "memory")

// ---------------------------------------------------------------- scratch
__device__ float g_wr[WR_TOT];                 // tf32-rounded weights, native layout
__device__ float g_xn[SEQ * HDIM];
__device__ float g_q[SEQ * HDIM];
__device__ float g_kv[2 * SEQ * 512];          // k | v
__device__ float g_scores[(size_t)NH * SEQ * SEQ];
__device__ float g_ao[SEQ * HDIM];
__device__ float g_h1[SEQ * HDIM];
__device__ float g_xf[SEQ * HDIM];
__device__ float g_gu[(size_t)NE * SEQ * GUW];
__device__ float g_hb[NE * SEQ * FF];
__device__ float g_slot[TKN * SEQ * HDIM];
__device__ int   g_cnt[NE];
__device__ int   g_tok[NE * SEQ];
__device__ int   g_orow[NE * SEQ];
__device__ float g_wt[NE * SEQ];

// ---------------------------------------------------------------- tf32 GEMM
// C[M,N] = A[M,K] @ op(B) (+resid). Operands pre-rounded to tf32.
// TB=0: B gmem [N,K] (K contiguous rows).  TB=1: B gmem [K,N] (N contiguous rows).
// Batched over z: A += sA*z, B += sB*(z/bzdiv), C += sC*z.
// Aidx: per-z row gather for A; Cidx: per-z row scatter for C; cnt: M override.
// causal: skip tiles with n0 > m0+127. kcausal: cap K at m0+128.
// roundC: round output to tf32 (when C feeds another GEMM as an operand).
template<int TB>
__global__ void __launch_bounds__(256, 2) tgemm_k(
    const float* __restrict__ A, const float* __restrict__ B,
    float* __restrict__ C, const float* __restrict__ resid,
    int M, int N, int K, int lda, int ldb, int ldc,
    long long sA, long long sB, long long sC, int bzdiv,
    const int* __restrict__ Aidx, const int* __restrict__ Cidx,
    const int* __restrict__ cnt, int causal, int kcausal, int roundC)
{
    int z = blockIdx.z;
    int Mz = cnt ? cnt[z] : M;
    int m0 = blockIdx.y * 128, n0 = blockIdx.x * 128;
    if (m0 >= Mz) return;
    if (causal && n0 > m0 + 127) return;
    int Keff = kcausal ? min(K, m0 + 128) : K;
    int nch = Keff >> 5;

    extern __shared__ float dsm[];
    uint32_t sb = smem_u32(dsm);

    int tid = threadIdx.x, lane = tid & 31, wid = tid >> 5;
    int wm = wid & 1, wn = wid >> 1;

    const float* Az = A + sA * z;
    const float* Bz = B + sB * (z / bzdiv);
    const int* aidx = Aidx ? Aidx + (size_t)z * SEQ : nullptr;

    // A copy map: thread -> (row am, granules g0..g0+3)
    int am = tid >> 1;
    int g0 = (tid & 1) * 4;
    const float* asrc; uint32_t avalid;
    {
        int gm = m0 + am;
        if (gm < Mz) {
            int ar = aidx ? aidx[gm] : gm;
            asrc = Az + (size_t)ar * lda + g0 * 4;
            avalid = 16u;
        } else { asrc = Az; avalid = 0u; }
    }
    uint32_t arow7 = (uint32_t)(am & 7);
    uint32_t abyte = (uint32_t)am << 7;

    // B copy maps
    const float* bsrc0 = nullptr;   // TB=0: row = n (am), cols k
    const float* bsrc1 = nullptr;   // TB=1: row = k (bk), cols n
    int bk = tid >> 3;              // 0..31
    int gb = tid & 7;               // 0..7
    uint32_t bbyte = (uint32_t)bk << 9;   // k * 512B
    uint32_t bk3 = (uint32_t)((bk & 3) << 1);
    if (TB == 0) bsrc0 = Bz + (size_t)(n0 + am) * ldb + g0 * 4;
    else         bsrc1 = Bz + (size_t)bk * ldb + n0 + gb * 4;

    float acc[4][4][4];
#pragma unroll
    for (int mf = 0; mf < 4; mf++)
#pragma unroll
        for (int nf = 0; nf < 4; nf++)
#pragma unroll
            for (int r = 0; r < 4; r++) acc[mf][nf][r] = 0.f;

    // prologue: stages 0,1
#pragma unroll
    for (int p = 0; p < 2; p++) {
        if (p < nch) {
            uint32_t stg = sb + (uint32_t)p * (STG_FLOATS * 4);
            const float* as = asrc + p * 32;
#pragma unroll
            for (int j = 0; j < 4; j++)
                cp16(stg + abyte + ((uint32_t)((g0 + j) ^ arow7) << 4), as + 4 * j, avalid);
            if (TB == 0) {
                const float* bs = bsrc0 + p * 32;
#pragma unroll
                for (int j = 0; j < 4; j++)
                    cp16(stg + 16384u + abyte + ((uint32_t)((g0 + j) ^ arow7) << 4), bs + 4 * j, 16u);
            } else {
                const float* bs = bsrc1 + (size_t)p * 32 * ldb;
#pragma unroll
                for (int j = 0; j < 4; j++)
                    cp16(stg + 16384u + bbyte + ((uint32_t)((gb + 8 * j) ^ bk3) << 4), bs + 32 * j, 16u);
            }
            CP_COMMIT();
        }
    }

    int c4 = lane & 3;
    int rowA[4], rowB[4], nphysB[4];
#pragma unroll
    for (int mf = 0; mf < 4; mf++) rowA[mf] = wm * 64 + mf * 16 + (lane >> 2);
#pragma unroll
    for (int nf = 0; nf < 4; nf++) {
        rowB[nf] = wn * 32 + nf * 8 + (lane >> 2);
        nphysB[nf] = rowB[nf] ^ (c4 << 3);
    }

    for (int i = 0; i < nch; i++) {
        CP_WAIT1();
        __syncthreads();

        if (i + 2 < nch) {
            uint32_t stg = sb + (uint32_t)((i + 2) % NSTG) * (STG_FLOATS * 4);
            const float* as = asrc + (i + 2) * 32;
#pragma unroll
            for (int j = 0; j < 4; j++)
                cp16(stg + abyte + ((uint32_t)((g0 + j) ^ arow7) << 4), as + 4 * j, avalid);
            if (TB == 0) {
                const float* bs = bsrc0 + (i + 2) * 32;
#pragma unroll
                for (int j = 0; j < 4; j++)
                    cp16(stg + 16384u + abyte + ((uint32_t)((g0 + j) ^ arow7) << 4), bs + 4 * j, 16u);
            } else {
                const float* bs = bsrc1 + (size_t)(i + 2) * 32 * ldb;
#pragma unroll
                for (int j = 0; j < 4; j++)
                    cp16(stg + 16384u + bbyte + ((uint32_t)((gb + 8 * j) ^ bk3) << 4), bs + 32 * j, 16u);
            }
            CP_COMMIT();
        }

        const uint32_t* sA32 = reinterpret_cast<const uint32_t*>(dsm + (i % NSTG) * STG_FLOATS);
        const uint32_t* sB32 = sA32 + 4096;

#pragma unroll
        for (int ks = 0; ks < 4; ks++) {
            int g = ks * 2;
            uint32_t af[4][4], bf[4][2];
#pragma unroll
            for (int mf = 0; mf < 4; mf++) {
                int r = rowA[mf], r8 = r + 8;
                af[mf][0] = sA32[(r  << 5) + (((g    ) ^ (r  & 7)) << 2) + c4];
                af[mf][1] = sA32[(r8 << 5) + (((g    ) ^ (r8 & 7)) << 2) + c4];
                af[mf][2] = sA32[(r  << 5) + (((g + 1) ^ (r  & 7)) << 2) + c4];
                af[mf][3] = sA32[(r8 << 5) + (((g + 1) ^ (r8 & 7)) << 2) + c4];
            }
            if (TB == 0) {
#pragma unroll
                for (int nf = 0; nf < 4; nf++) {
                    int r = rowB[nf];
                    bf[nf][0] = sB32[(r << 5) + (((g    ) ^ (r & 7)) << 2) + c4];
                    bf[nf][1] = sB32[(r << 5) + (((g + 1) ^ (r & 7)) << 2) + c4];
                }
            } else {
#pragma unroll
                for (int nf = 0; nf < 4; nf++) {
                    int base = (ks * 8 + c4) * 128 + nphysB[nf];
                    bf[nf][0] = sB32[base];
                    bf[nf][1] = sB32[base + 512];
                }
            }
#pragma unroll
            for (int mf = 0; mf < 4; mf++)
#pragma unroll
                for (int nf = 0; nf < 4; nf++)
                    mma_tf32(acc[mf][nf], af[mf], bf[nf]);
        }
    }

    // ---- epilogue ----
    float* Cz = C + sC * z;
    const int* cidx = Cidx ? Cidx + (size_t)z * SEQ : nullptr;
#pragma unroll
    for (int mf = 0; mf < 4; mf++) {
#pragma unroll
        for (int half = 0; half < 2; half++) {
            int gm = m0 + wm * 64 + mf * 16 + (lane >> 2) + half * 8;
            if (gm >= Mz) continue;
            int cr = cidx ? cidx[gm] : gm;
            float* crow = Cz + (size_t)cr * ldc;
            const float* rrow = resid ? resid + (size_t)cr * ldc : nullptr;
#pragma unroll
            for (int nf = 0; nf < 4; nf++) {
                int gc = n0 + wn * 32 + nf * 8 + (lane & 3) * 2;
                float2 v;
                v.x = acc[mf][nf][half * 2 + 0];
                v.y = acc[mf][nf][half * 2 + 1];
                if (rrow) { v.x += rrow[gc]; v.y += rrow[gc + 1]; }
                if (roundC) { v.x = f2tf_f(v.x); v.y = f2tf_f(v.y); }
                *reinterpret_cast<float2*>(crow + gc) = v;
            }
        }
    }
}

// ---------------------------------------------------------------- round copy
__global__ void roundcpy_k(const float4* __restrict__ in, float4* __restrict__ out)
{
    size_t i = (size_t)blockIdx.x * 256 + threadIdx.x;
    float4 v = in[i];
    v.x = f2tf_f(v.x); v.y = f2tf_f(v.y); v.z = f2tf_f(v.z); v.w = f2tf_f(v.w);
    out[i] = v;
}

// ---------------------------------------------------------------- aux kernels
__global__ void rmsnorm_k(const float* __restrict__ x, const float* __restrict__ w,
                          float* __restrict__ o, float* __restrict__ ofull)
{
    int t = blockIdx.x, tid = threadIdx.x;
    const float* xr = x + (size_t)t * HDIM;
    float s = 0.f;
    for (int h = tid; h < HDIM; h += 256) { float v = xr[h]; s += v * v; }
    __shared__ float red[256];
    red[tid] = s; __syncthreads();
    for (int st = 128; st > 0; st >>= 1) {
        if (tid < st) red[tid] += red[tid + st];
        __syncthreads();
    }
    float inv = rsqrtf(red[0] / (float)HDIM + 1e-6f);
    float* orow = o + (size_t)t * HDIM;
    float* frow = ofull ? ofull + (size_t)t * HDIM : nullptr;
    for (int h = tid; h < HDIM; h += 256) {
        float v = w[h] * xr[h] * inv;
        orow[h] = f2tf_f(v);
        if (frow) frow[h] = v;
    }
}

__global__ void rope_k(float* __restrict__ x, int ld, const float* __restrict__ cosb,
                       const float* __restrict__ sinb)
{
    int s = blockIdx.x, h = blockIdx.y, d = threadIdx.x;
    float* r = x + (size_t)s * ld + h * HD;
    float v = r[d];
    float w = (d < 64) ? r[d ^ 32] : 0.f;
    __syncthreads();
    if (d < 32)      r[d] = f2tf_f(v * cosb[s * RD + d] - w * sinb[s * RD + d]);
    else if (d < 64) r[d] = f2tf_f(v * cosb[s * RD + d] + w * sinb[s * RD + d]);
}

__global__ void softmax_k(float* __restrict__ sc, const float* __restrict__ sink)
{
    int i = blockIdx.x, h = blockIdx.y, tid = threadIdx.x;
    float* row = sc + ((size_t)h * SEQ + i) * (size_t)SEQ;
    const float scale = 0.08838834764831845f;
    __shared__ float red[256];

    float lv[8];
    float m = -1e30f;
#pragma unroll
    for (int c = 0; c < 8; c++) {
        int j = tid + (c << 8);
        if (j <= i) { float v = row[j] * scale; lv[c] = v; m = fmaxf(m, v); }
    }
    red[tid] = m; __syncthreads();
    for (int st = 128; st > 0; st >>= 1) {
        if (tid < st) red[tid] = fmaxf(red[tid], red[tid + st]);
        __syncthreads();
    }
    m = red[0]; __syncthreads();

    float s = 0.f;
#pragma unroll
    for (int c = 0; c < 8; c++) {
        int j = tid + (c << 8);
        if (j <= i) { lv[c] = expf(lv[c] - m); s += lv[c]; }
    }
    red[tid] = s; __syncthreads();
    for (int st = 128; st > 0; st >>= 1) {
        if (tid < st) red[tid] += red[tid + st];
        __syncthreads();
    }
    float inv = 1.f / (red[0] + expf(sink[h] - m));

    // AV GEMM reads only k < kcap for this row (kcausal tile cap)
    int kcap = min(SEQ, ((i >> 7) + 1) << 7);
#pragma unroll
    for (int c = 0; c < 8; c++) {
        int j = tid + (c << 8);
        if (j < kcap) row[j] = (j <= i) ? f2tf_f(lv[c] * inv) : 0.f;
    }
}

__global__ void zero_cnt_k(int* cnt) { if (threadIdx.x < NE) cnt[threadIdx.x] = 0; }

__global__ void router_k(const float* __restrict__ xf, const float* __restrict__ gw,
                         const float* __restrict__ gbias, int* cnt, int* tok,
                         int* orow, float* wt)
{
    int t = blockIdx.x, tid = threadIdx.x;
    int lane = tid & 31, wid = tid >> 5;
    __shared__ float logits[NE];
    const float* xr = xf + (size_t)t * HDIM;

    for (int e = wid; e < NE; e += 8) {
        const float* gr = gw + (size_t)e * HDIM;
        float p = 0.f;
        for (int hh = lane; hh < HDIM; hh += 32) p += xr[hh] * gr[hh];
        for (int off = 16; off > 0; off >>= 1) p += __shfl_down_sync(0xffffffffu, p, off);
        if (lane == 0) logits[e] = p;
    }
    __syncthreads();

    if (tid == 0) {
        float sg[NE], sfc[NE];
        for (int e = 0; e < NE; e++) {
            sg[e] = 1.f / (1.f + expf(-logits[e]));
            sfc[e] = sg[e] + gbias[e];
        }
        float gs[4];
        for (int g = 0; g < 4; g++) {
            float m1 = -1e30f, m2 = -1e30f;
            for (int j = 0; j < 4; j++) {
                float v = sfc[g * 4 + j];
                if (v > m1) { m2 = m1; m1 = v; } else if (v > m2) m2 = v;
            }
            gs[g] = m1 + m2;
        }
        int g1 = 0;
        for (int g = 1; g < 4; g++) if (gs[g] > gs[g1]) g1 = g;
        int g2 = -1;
        for (int g = 0; g < 4; g++) {
            if (g == g1) continue;
            if (g2 < 0 || gs[g] > gs[g2]) g2 = g;
        }
        bool allow[NE];
        for (int e = 0; e < NE; e++) { int g = e >> 2; allow[e] = (g == g1 || g == g2); }

        int idx[TKN]; float tws[TKN]; float sum = 0.f;
        bool used[NE] = {};
        for (int j = 0; j < TKN; j++) {
            int bi = -1; float bv = -1e30f;
            for (int e = 0; e < NE; e++)
                if (allow[e] && !used[e] && sfc[e] > bv) { bv = sfc[e]; bi = e; }
            used[bi] = true; idx[j] = bi; tws[j] = sg[bi]; sum += tws[j];
        }
        float invs = 2.5f / (sum + 1e-20f);
        for (int j = 0; j < TKN; j++) {
            int e = idx[j];
            int pos = atomicAdd(&cnt[e], 1);
            tok[e * SEQ + pos]  = t;
            orow[e * SEQ + pos] = j * SEQ + t;
            wt[e * SEQ + pos]   = tws[j] * invs;
        }
    }
}

__global__ void silu_k(const float* __restrict__ gu, float* __restrict__ hb,
                       const float* __restrict__ wt, const int* __restrict__ cnt)
{
    int e = blockIdx.y, r = blockIdx.x;
    if (r >= cnt[e]) return;
    float w = wt[e * SEQ + r];
    const float* g = gu + ((size_t)e * SEQ + r) * GUW;
    float* o = hb + ((size_t)e * SEQ + r) * FF;
    for (int f = threadIdx.x; f < FF; f += 256) {
        float gv = g[f], uv = g[FF + f];
        float sig = 1.f / (1.f + expf(-gv));
        o[f] = f2tf_f(gv * sig * uv * w);
    }
}

__global__ void final_k(const float* __restrict__ h1, const float* __restrict__ slot,
                        float* __restrict__ out)
{
    size_t i = (size_t)blockIdx.x * 256 + threadIdx.x;
    const size_t NTOT = (size_t)SEQ * HDIM;
    out[i] = h1[i] + slot[i] + slot[NTOT + i] + slot[2 * NTOT + i] + slot[3 * NTOT + i];
}

// ---------------------------------------------------------------- launch
extern "C" void kernel_launch(void* const* d_in, const int* in_sizes, int n_in,
                              void* d_out, int out_size)
{
    const float* x      = (const float*)d_in[0];
    const float* cosb   = (const float*)d_in[1];
    const float* sinb   = (const float*)d_in[2];
    const float* ln1    = (const float*)d_in[3];
    const float* ln2    = (const float*)d_in[4];
    const float* Wq     = (const float*)d_in[5];
    const float* Wk     = (const float*)d_in[6];
    const float* Wv     = (const float*)d_in[7];
    const float* Wo     = (const float*)d_in[8];
    const float* sink   = (const float*)d_in[9];
    const float* gate_w = (const float*)d_in[10];
    const float* gate_b = (const float*)d_in[11];
    const float* Weg    = (const float*)d_in[12];
    const float* Weu    = (const float*)d_in[13];
    const float* Wed    = (const float*)d_in[14];
    float* out = (float*)d_out;

    cudaFuncSetAttribute(tgemm_k<0>, cudaFuncAttributeMaxDynamicSharedMemorySize, DSMEM_BYTES);
    cudaFuncSetAttribute(tgemm_k<1>, cudaFuncAttributeMaxDynamicSharedMemorySize, DSMEM_BYTES);

    void *p_wr, *p_xn, *p_q, *p_kv, *p_sc, *p_ao, *p_h1, *p_xf,
         *p_gu, *p_hb, *p_slot, *p_cnt, *p_tok, *p_orow, *p_wt;
    cudaGetSymbolAddress(&p_wr, g_wr);
    cudaGetSymbolAddress(&p_xn, g_xn);
    cudaGetSymbolAddress(&p_q, g_q);
    cudaGetSymbolAddress(&p_kv, g_kv);
    cudaGetSymbolAddress(&p_sc, g_scores);
    cudaGetSymbolAddress(&p_ao, g_ao);
    cudaGetSymbolAddress(&p_h1, g_h1);
    cudaGetSymbolAddress(&p_xf, g_xf);
    cudaGetSymbolAddress(&p_gu, g_gu);
    cudaGetSymbolAddress(&p_hb, g_hb);
    cudaGetSymbolAddress(&p_slot, g_slot);
    cudaGetSymbolAddress(&p_cnt, g_cnt);
    cudaGetSymbolAddress(&p_tok, g_tok);
    cudaGetSymbolAddress(&p_orow, g_orow);
    cudaGetSymbolAddress(&p_wt, g_wt);

    float* wr   = (float*)p_wr;
    float* xn   = (float*)p_xn;
    float* qbuf = (float*)p_q;
    float* kbuf = (float*)p_kv;
    float* vbuf = kbuf + (size_t)SEQ * 512;
    float* sc   = (float*)p_sc;
    float* ao   = (float*)p_ao;
    float* h1   = (float*)p_h1;
    float* xf   = (float*)p_xf;
    float* gu   = (float*)p_gu;
    float* hb   = (float*)p_hb;
    float* slot = (float*)p_slot;
    int* cnt = (int*)p_cnt; int* tok = (int*)p_tok; int* orow = (int*)p_orow;
    float* wt = (float*)p_wt;

    zero_cnt_k<<<1, 32>>>(cnt);

    // streaming tf32 rounding of weights (native layout preserved)
    roundcpy_k<<<4194304 / 1024, 256>>>((const float4*)Wq,  (float4*)(wr + WQ_OFF));
    roundcpy_k<<<1048576 / 1024, 256>>>((const float4*)Wk,  (float4*)(wr + WK_OFF));
    roundcpy_k<<<1048576 / 1024, 256>>>((const float4*)Wv,  (float4*)(wr + WV_OFF));
    roundcpy_k<<<4194304 / 1024, 256>>>((const float4*)Wo,  (float4*)(wr + WO_OFF));
    roundcpy_k<<<16777216 / 1024, 256>>>((const float4*)Weg, (float4*)(wr + WEG_OFF));
    roundcpy_k<<<16777216 / 1024, 256>>>((const float4*)Weu, (float4*)(wr + WEU_OFF));
    roundcpy_k<<<16777216 / 1024, 256>>>((const float4*)Wed, (float4*)(wr + WED_OFF));

    rmsnorm_k<<<SEQ, 256>>>(x, ln1, xn, nullptr);

    // Q projection
    tgemm_k<1><<<dim3(16, 16, 1), 256, DSMEM_BYTES>>>(
        xn, wr + WQ_OFF, qbuf, nullptr, SEQ, 2048, 2048, 2048, 2048, 2048,
        0, 0, 0, 1, nullptr, nullptr, nullptr, 0, 0, 1);
    // K|V projections batched over z (Wk and Wv adjacent in wr)
    tgemm_k<1><<<dim3(4, 16, 2), 256, DSMEM_BYTES>>>(
        xn, wr + WK_OFF, kbuf, nullptr, SEQ, 512, 2048, 2048, 512, 512,
        0, 1048576, (long long)SEQ * 512, 1, nullptr, nullptr, nullptr, 0, 0, 1);

    rope_k<<<dim3(SEQ, NH), 128>>>(qbuf, 2048, cosb, sinb);
    rope_k<<<dim3(SEQ, NKV), 128>>>(kbuf, 512, cosb, sinb);

    // scores[h] = q[h] @ k[h/4]^T  (B = kbuf rows [N=seq][K=HD])
    tgemm_k<0><<<dim3(16, 16, NH), 256, DSMEM_BYTES>>>(
        qbuf, kbuf, sc, nullptr, SEQ, SEQ, HD, 2048, 512, SEQ,
        128, 128, (long long)SEQ * SEQ, NH / NKV,
        nullptr, nullptr, nullptr, 1, 0, 0);

    softmax_k<<<dim3(SEQ, NH), 256>>>(sc, sink);

    // ao[:, h*128..] = probs[h] @ v[h/4]  (B = vbuf [K=seq][N=HD] native)
    tgemm_k<1><<<dim3(1, 16, NH), 256, DSMEM_BYTES>>>(
        sc, vbuf, ao, nullptr, SEQ, HD, SEQ, SEQ, 512, 2048,
        (long long)SEQ * SEQ, 128, 128, NH / NKV,
        nullptr, nullptr, nullptr, 0, 1, 1);

    // h1 = ao @ Wo + x
    tgemm_k<1><<<dim3(16, 16, 1), 256, DSMEM_BYTES>>>(
        ao, wr + WO_OFF, h1, x, SEQ, 2048, 2048, 2048, 2048, 2048,
        0, 0, 0, 1, nullptr, nullptr, nullptr, 0, 0, 0);

    // xf (tf32 for GEMM) + xn reused as unrounded copy for the router
    rmsnorm_k<<<SEQ, 256>>>(h1, ln2, xf, xn);
    router_k<<<SEQ, 256>>>(xn, gate_w, gate_b, cnt, tok, orow, wt);

    // expert gate / up projections (row-gathered A)
    tgemm_k<1><<<dim3(4, 16, NE), 256, DSMEM_BYTES>>>(
        xf, wr + WEG_OFF, gu, nullptr, SEQ, FF, 2048, 2048, FF, GUW,
        0, (long long)2048 * FF, (long long)SEQ * GUW, 1,
        tok, nullptr, cnt, 0, 0, 0);
    tgemm_k<1><<<dim3(4, 16, NE), 256, DSMEM_BYTES>>>(
        xf, wr + WEU_OFF, gu + FF, nullptr, SEQ, FF, 2048, 2048, FF, GUW,
        0, (long long)2048 * FF, (long long)SEQ * GUW, 1,
        tok, nullptr, cnt, 0, 0, 0);

    silu_k<<<dim3(SEQ, NE), 256>>>(gu, hb, wt, cnt);

    // down projection, scattered to per-(slot,token) rows
    tgemm_k<1><<<dim3(16, 16, NE), 256, DSMEM_BYTES>>>(
        hb, wr + WED_OFF, slot, nullptr, SEQ, 2048, FF, FF, 2048, 2048,
        (long long)SEQ * FF, (long long)FF * 2048, 0, 1,
        nullptr, orow, cnt, 0, 0, 0);

    final_k<<<(SEQ * HDIM) / 256, 256>>>(h1, slot, out);
}